// round 14
// baseline (speedup 1.0000x reference)
#include <cuda_runtime.h>
#include <cuda_fp16.h>
#include <cstdint>
#include <math.h>

// Problem dims (fixed)
static constexpr int DIM_N = 4096;  // samples
static constexpr int DIM_D = 512;   // feature dim
static constexpr int DIM_M = 4096;  // M columns
static constexpr int DIM_K = 2048;  // centroids
static constexpr int ZSPLIT = 8;    // split-K factor for S = X^T X
static constexpr int DIM_CM = DIM_K + DIM_M;  // stacked [C; Mt] rows = 6144

// ---------------- scratch (device globals; allocation-free) ----------------
__device__ __half g_Xt_hi[DIM_D * DIM_N];    // X^T  [512, 4096]
__device__ __half g_CM_hi[DIM_CM * DIM_D];   // [C; M^T]  [6144, 512]
__device__ __half g_CM_lo[DIM_CM * DIM_D];
__device__ __half g_S_hi[DIM_D * DIM_D];     // S    [512, 512]
__device__ __half g_U_hi[DIM_K * DIM_D];     // U = C@S  [2048, 512]
__device__ float g_Spart[ZSPLIT * DIM_D * DIM_D];   // split-K partials
__device__ float g_dotp[4 * DIM_CM];                // per-col-band dot partials
__device__ float g_xm2[DIM_M];
__device__ float g_xc2[DIM_K];

// ---------------------------- warp-MMA helpers ------------------------------
__device__ __forceinline__ uint32_t smem_u32(const void* p) {
    uint32_t a;
    asm("{ .reg .u64 t; cvta.to.shared.u64 t, %1; cvt.u32.u64 %0, t; }" : "=r"(a) : "l"(p));
    return a;
}
__device__ __forceinline__ void ldm_x4(uint32_t* r, uint32_t addr) {
    asm volatile("ldmatrix.sync.aligned.m8n8.x4.shared.b16 {%0,%1,%2,%3}, [%4];"
                 : "=r"(r[0]), "=r"(r[1]), "=r"(r[2]), "=r"(r[3]) : "r"(addr));
}
__device__ __forceinline__ void mma_f16(float* c, const uint32_t* a, const uint32_t* b) {
    asm volatile("mma.sync.aligned.m16n8k16.row.col.f32.f16.f16.f32 "
                 "{%0,%1,%2,%3}, {%4,%5,%6,%7}, {%8,%9}, {%0,%1,%2,%3};"
                 : "+f"(c[0]), "+f"(c[1]), "+f"(c[2]), "+f"(c[3])
                 : "r"(a[0]), "r"(a[1]), "r"(a[2]), "r"(a[3]), "r"(b[0]), "r"(b[1]));
}
#define CP_ASYNC16(dst, src) \
    asm volatile("cp.async.cg.shared.global [%0], [%1], 16;" :: "r"(dst), "l"(src))
#define CP_COMMIT() asm volatile("cp.async.commit_group;" ::: "memory")
#define CP_WAIT1()  asm volatile("cp.async.wait_group 1;" ::: "memory")
#define CP_WAIT0()  asm volatile("cp.async.wait_group 0;" ::: "memory")

// 128B-row smem layout with XOR swizzle: 16B chunk column ^= (row & 7).
__device__ __forceinline__ uint32_t swz(uint32_t row, uint32_t col) {
    return row * 128 + (col ^ ((row & 7) << 4));
}

// ---------------------------------------------------------------------------
// Single-product fp16 GEMM via mma.sync:  G[i,j] = sum_k Ahi[i,k] * Bhi[j,k]
// A [Mo,Ktot] K-major fp16, B [No,Ktot] K-major fp16.
// CTA tile 128x128, K-slab 64, 256 threads = 8 warps (2x4), warp tile 64x32.
// 3-stage cp.async pipeline, 32KB stages (96KB smem, 2 CTA/SM).
// MODE 0: write fp32 Cout (with z-split offsets).
// MODE 1: fused distance epilogue: out = sqrt(max(colAdd[c] - 2g + rowAdd[r],0)).
// MODE 2: UT mode (Ktot==No==512): fp16 G -> Uhi (rows < DIM_K) + per-CTA-band
//         dot partials dotp[bx*DIM_CM+row] = sum_{c in band} (Ahi+Alo)[row,c]*G[row,c].
// ---------------------------------------------------------------------------
static constexpr int TILE_BYTES = 128 * 128;           // 16384
static constexpr int STAGE_BYTES = 2 * TILE_BYTES;     // 32768
static constexpr int GEMM_SMEM = 3 * STAGE_BYTES;      // 98304

template <int MODE>
__global__ __launch_bounds__(256, 2)
void f16s_gemm(const __half* __restrict__ Ahi, const __half* __restrict__ Alo,
               const __half* __restrict__ Bhi,
               float* __restrict__ Cout,
               int No, int Ktot, int kspan, size_t zstride,
               const float* __restrict__ rowAdd, const float* __restrict__ colAdd,
               __half* __restrict__ Uhi, float* __restrict__ dotp)
{
    extern __shared__ __align__(128) unsigned char smem[];
    const uint32_t sbase = smem_u32(smem);
    const uint32_t OFF_AHI = 0, OFF_BHI = TILE_BYTES;

    const int tid = threadIdx.x;
    const int wid = tid >> 5;
    const int lane = tid & 31;
    const int warp_m = wid >> 2;     // 0..1 -> 64 rows each
    const int warp_n = wid & 3;      // 0..3 -> 32 cols each
    const int rowA0 = blockIdx.y * 128;
    const int rowB0 = blockIdx.x * 128;
    const int kz = blockIdx.z * kspan;
    const int nslabs = kspan / 64;
    if (MODE == 0) Cout += (size_t)blockIdx.z * zstride;

    float acc[4][4][4];
#pragma unroll
    for (int i = 0; i < 4; i++)
#pragma unroll
        for (int j = 0; j < 4; j++)
#pragma unroll
            for (int v = 0; v < 4; v++) acc[i][j][v] = 0.0f;

    // ldmatrix lane addressing (k-invariant parts)
    const int a_row = warp_m * 64 + (lane & 15);
    const uint32_t a_coff = (uint32_t)((lane >> 4) << 4);
    const int b_row = warp_n * 32 + ((lane >> 4) << 3) + (lane & 7);
    const uint32_t b_coff = (uint32_t)(((lane >> 3) & 1) << 4);

    auto load_slab = [&](int slab, int stage) {
        const int kbase = kz + slab * 64;
        const uint32_t st = (uint32_t)stage * STAGE_BYTES;
#pragma unroll
        for (int i = 0; i < 4; i++) {
            const int idx = tid + i * 256;       // 0..1023
            const int r = idx >> 3;
            const int c = idx & 7;               // 16B chunk within 128B row
            const size_t aoff = (size_t)(rowA0 + r) * Ktot + kbase + c * 8;
            const size_t boff = (size_t)(rowB0 + r) * Ktot + kbase + c * 8;
            const uint32_t so = st + swz((uint32_t)r, (uint32_t)(c * 16));
            CP_ASYNC16(sbase + OFF_AHI + so, Ahi + aoff);
            CP_ASYNC16(sbase + OFF_BHI + so, Bhi + boff);
        }
    };

    // 3-stage pipeline: prefetch distance 2.
    load_slab(0, 0); CP_COMMIT();
    if (nslabs > 1) { load_slab(1, 1); CP_COMMIT(); }

    for (int slab = 0; slab < nslabs; slab++) {
        if (slab + 2 < nslabs) { CP_WAIT1(); } else { CP_WAIT0(); }
        __syncthreads();          // slab data visible; stage (slab+2)%3 free
        if (slab + 2 < nslabs) {
            load_slab(slab + 2, (slab + 2) % 3);
            CP_COMMIT();
        }

        const uint32_t st = (uint32_t)(slab % 3) * STAGE_BYTES;
#pragma unroll
        for (int kk = 0; kk < 4; kk++) {         // four k16 steps per slab
            const uint32_t kcol = kk * 32;
            uint32_t a_hi[4][4], b_hi[2][4];
#pragma unroll
            for (int mi = 0; mi < 4; mi++) {
                const uint32_t ar = st + swz((uint32_t)(a_row + mi * 16), kcol + a_coff);
                ldm_x4(a_hi[mi], sbase + OFF_AHI + ar);
            }
#pragma unroll
            for (int p = 0; p < 2; p++) {        // nj pairs {0,1}, {2,3}
                const uint32_t br = st + swz((uint32_t)(b_row + p * 16), kcol + b_coff);
                ldm_x4(b_hi[p], sbase + OFF_BHI + br);
            }
#pragma unroll
            for (int mi = 0; mi < 4; mi++)
#pragma unroll
                for (int nj = 0; nj < 4; nj++)
                    mma_f16(acc[mi][nj], a_hi[mi], &b_hi[nj >> 1][(nj & 1) * 2]);
        }
    }

    // ---------------- epilogue ----------------
    // c-frag layout: c0,c1 -> row lane/4, cols (lane%4)*2+{0,1}; c2,c3 -> row+8
    const int er0 = rowA0 + warp_m * 64 + (lane >> 2);
    const int ec0 = rowB0 + warp_n * 32 + (lane & 3) * 2;

    if (MODE == 2) {
        __syncthreads();                          // mainloop smem reuse
        float* sm_dot = (float*)smem;             // [128 rows][4 warp_n]
#pragma unroll
        for (int mi = 0; mi < 4; mi++) {
#pragma unroll
            for (int half = 0; half < 2; half++) {
                const int row = er0 + mi * 16 + half * 8;
                float rs = 0.0f;
#pragma unroll
                for (int nj = 0; nj < 4; nj++) {
                    const int col = ec0 + nj * 8;
                    float2 v;
                    v.x = acc[mi][nj][half * 2 + 0];
                    v.y = acc[mi][nj][half * 2 + 1];
                    // A value at (row, col) in fp32 (hi+lo)
                    const size_t o = (size_t)row * Ktot + col;
                    const float ax = __half2float(Ahi[o])     + __half2float(Alo[o]);
                    const float ay = __half2float(Ahi[o + 1]) + __half2float(Alo[o + 1]);
                    rs = fmaf(ax, v.x, rs);
                    rs = fmaf(ay, v.y, rs);
                    if (row < DIM_K) {            // write U (fp16 hi only)
                        __half2 h2;
                        h2.x = __float2half_rn(v.x);
                        h2.y = __float2half_rn(v.y);
                        *(__half2*)(Uhi + (size_t)row * DIM_D + col) = h2;
                    }
                }
                rs += __shfl_xor_sync(0xFFFFFFFFu, rs, 1);
                rs += __shfl_xor_sync(0xFFFFFFFFu, rs, 2);
                if ((lane & 3) == 0) {
                    const int lr = warp_m * 64 + mi * 16 + half * 8 + (lane >> 2);
                    sm_dot[lr * 4 + warp_n] = rs;
                }
            }
        }
        __syncthreads();
        if (tid < 128) {
            const float s = sm_dot[tid * 4] + sm_dot[tid * 4 + 1]
                          + sm_dot[tid * 4 + 2] + sm_dot[tid * 4 + 3];
            dotp[(size_t)blockIdx.x * DIM_CM + rowA0 + tid] = s;
        }
        return;
    }

#pragma unroll
    for (int mi = 0; mi < 4; mi++) {
#pragma unroll
        for (int half = 0; half < 2; half++) {
            const int row = er0 + mi * 16 + half * 8;
            float radd = 0.0f;
            if (MODE == 1) radd = rowAdd[row];
#pragma unroll
            for (int nj = 0; nj < 4; nj++) {
                const int col = ec0 + nj * 8;
                float2 v;
                v.x = acc[mi][nj][half * 2 + 0];
                v.y = acc[mi][nj][half * 2 + 1];
                if (MODE == 1) {
                    const float2 ca = *(const float2*)(colAdd + col);
                    v.x = sqrtf(fmaxf(ca.x - 2.0f * v.x + radd, 0.0f));
                    v.y = sqrtf(fmaxf(ca.y - 2.0f * v.y + radd, 0.0f));
                }
                *(float2*)(Cout + (size_t)row * No + col) = v;
            }
        }
    }
}

// ------------------------- conversion / small kernels -----------------------
__global__ void split_kernel(const float* __restrict__ in,
                             __half* __restrict__ hi,
                             __half* __restrict__ lo, int n)
{
    const int i = blockIdx.x * blockDim.x + threadIdx.x;
    if (i >= n) return;
    const float x = in[i];
    const __half h = __float2half_rn(x);
    hi[i] = h;
    lo[i] = __float2half_rn(x - __half2float(h));
}

// in [R,C] fp32 -> hi (and optionally lo) [C,R] fp16 (transpose)
__global__ void split_transpose_kernel(const float* __restrict__ in,
                                       __half* __restrict__ hi,
                                       __half* __restrict__ lo, int R, int C)
{
    __shared__ float t[32][33];
    const int x = blockIdx.x * 32 + threadIdx.x;
    const int y0 = blockIdx.y * 32;
#pragma unroll
    for (int j = 0; j < 32; j += 8)
        t[threadIdx.y + j][threadIdx.x] = in[(size_t)(y0 + threadIdx.y + j) * C + x];
    __syncthreads();
#pragma unroll
    for (int j = 0; j < 32; j += 8) {
        const int c = blockIdx.x * 32 + threadIdx.y + j;
        const int r = y0 + threadIdx.x;
        const float v = t[threadIdx.x][threadIdx.y + j];
        const __half h = __float2half_rn(v);
        hi[(size_t)c * R + r] = h;
        if (lo) lo[(size_t)c * R + r] = __float2half_rn(v - __half2float(h));
    }
}

// sum split-K partials of S -> fp16 hi
__global__ void reduce_split_kernel(const float* __restrict__ part,
                                    __half* __restrict__ hi, int n)
{
    const int i = blockIdx.x * blockDim.x + threadIdx.x;
    if (i >= n) return;
    float acc = 0.0f;
#pragma unroll
    for (int z = 0; z < ZSPLIT; z++) acc += part[i + (size_t)z * n];
    hi[i] = __float2half_rn(acc);
}

__global__ void combine_dots_kernel(const float* __restrict__ dotp,
                                    float* __restrict__ xc2, float* __restrict__ xm2)
{
    const int i = blockIdx.x * blockDim.x + threadIdx.x;
    if (i >= DIM_CM) return;
    const float s = dotp[i] + dotp[DIM_CM + i] + dotp[2 * DIM_CM + i] + dotp[3 * DIM_CM + i];
    if (i < DIM_K) xc2[i] = s;
    else           xm2[i - DIM_K] = s;
}

// --------------------------------- launch ----------------------------------
extern "C" void kernel_launch(void* const* d_in, const int* in_sizes, int n_in,
                              void* d_out, int out_size)
{
    const float* X = (const float*)d_in[0];  // [4096, 512]
    const float* M = (const float*)d_in[1];  // [512, 4096]
    const float* C = (const float*)d_in[2];  // [2048, 512]
    float* out = (float*)d_out;              // [2048, 4096]

    // one-time setup on the (uncaptured) correctness call
    static bool init_done = false;
    static cudaStream_t s2;
    static cudaEvent_t ev_fork, ev_join;
    if (!init_done) {
        cudaFuncSetAttribute(f16s_gemm<0>, cudaFuncAttributeMaxDynamicSharedMemorySize, GEMM_SMEM);
        cudaFuncSetAttribute(f16s_gemm<1>, cudaFuncAttributeMaxDynamicSharedMemorySize, GEMM_SMEM);
        cudaFuncSetAttribute(f16s_gemm<2>, cudaFuncAttributeMaxDynamicSharedMemorySize, GEMM_SMEM);
        cudaStreamCreateWithFlags(&s2, cudaStreamNonBlocking);
        cudaEventCreateWithFlags(&ev_fork, cudaEventDisableTiming);
        cudaEventCreateWithFlags(&ev_join, cudaEventDisableTiming);
        init_done = true;
    }

    __half *Xt_hi, *CM_hi, *CM_lo, *S_hi, *U_hi;
    float *Spart, *dotp, *xm2, *xc2;
    cudaGetSymbolAddress((void**)&Xt_hi, g_Xt_hi);
    cudaGetSymbolAddress((void**)&CM_hi, g_CM_hi);
    cudaGetSymbolAddress((void**)&CM_lo, g_CM_lo);
    cudaGetSymbolAddress((void**)&S_hi,  g_S_hi);
    cudaGetSymbolAddress((void**)&U_hi,  g_U_hi);
    cudaGetSymbolAddress((void**)&Spart, g_Spart);
    cudaGetSymbolAddress((void**)&dotp,  g_dotp);
    cudaGetSymbolAddress((void**)&xm2,   g_xm2);
    cudaGetSymbolAddress((void**)&xc2,   g_xc2);

    __half* Mt_hi = CM_hi + (size_t)DIM_K * DIM_D;  // rows 2048..6143
    __half* Mt_lo = CM_lo + (size_t)DIM_K * DIM_D;

    // Fork: side stream handles CM transforms (needed only by UT) while the
    // main stream runs the X transform -> S-GEMM -> reduce chain.
    cudaEventRecord(ev_fork, 0);
    cudaStreamWaitEvent(s2, ev_fork, 0);

    // side stream: CM = [C; M^T]  [6144,512]
    split_kernel<<<(DIM_K * DIM_D) / 256, 256, 0, s2>>>(C, CM_hi, CM_lo, DIM_K * DIM_D);
    split_transpose_kernel<<<dim3(DIM_M / 32, DIM_D / 32), dim3(32, 8), 0, s2>>>(M, Mt_hi, Mt_lo, DIM_D, DIM_M);
    cudaEventRecord(ev_join, s2);

    // main stream: Xt (hi only), S = Xt_hi @ Xt_hi^T with split-K=8, reduce
    split_transpose_kernel<<<dim3(DIM_D / 32, DIM_N / 32), dim3(32, 8)>>>(X, Xt_hi, nullptr, DIM_N, DIM_D);
    f16s_gemm<0><<<dim3(DIM_D / 128, DIM_D / 128, ZSPLIT), 256, GEMM_SMEM>>>(
        Xt_hi, nullptr, Xt_hi, Spart,
        DIM_D, DIM_N, DIM_N / ZSPLIT, (size_t)DIM_D * DIM_D,
        nullptr, nullptr, nullptr, nullptr);
    reduce_split_kernel<<<(DIM_D * DIM_D) / 256, 256>>>(Spart, S_hi, DIM_D * DIM_D);

    // join: UT needs CM + S
    cudaStreamWaitEvent(0, ev_join, 0);

    // UT = CM_hi @ S_hi  (MODE2: writes U_hi for C rows + dot partials)
    f16s_gemm<2><<<dim3(DIM_D / 128, DIM_CM / 128, 1), 256, GEMM_SMEM>>>(
        CM_hi, CM_lo, S_hi, nullptr, DIM_D, DIM_D, DIM_D, 0,
        nullptr, nullptr, U_hi, dotp);

    // xc2[k] = c_k^T S c_k ; xm2[m] = m^T S m
    combine_dots_kernel<<<(DIM_CM + 255) / 256, 256>>>(dotp, xc2, xm2);

    // out[k,m] = sqrt(max(xm2[m] - 2*(U_hi @ Mt_hi^T)[k,m] + xc2[k], 0))
    f16s_gemm<1><<<dim3(DIM_M / 128, DIM_K / 128, 1), 256, GEMM_SMEM>>>(
        U_hi, nullptr, Mt_hi, out, DIM_M, DIM_D, DIM_D, 0,
        xc2, xm2, nullptr, nullptr);
}

// round 15
// speedup vs baseline: 1.1533x; 1.1533x over previous
#include <cuda_runtime.h>
#include <cuda_fp16.h>
#include <cstdint>
#include <math.h>

// Problem dims (fixed)
static constexpr int DIM_N = 4096;  // samples
static constexpr int DIM_D = 512;   // feature dim
static constexpr int DIM_M = 4096;  // M columns
static constexpr int DIM_K = 2048;  // centroids
static constexpr int ZSPLIT = 8;    // split-K factor for S = X^T X
static constexpr int DIM_CM = DIM_K + DIM_M;  // stacked [C; Mt] rows = 6144

// ---------------- scratch (device globals; allocation-free) ----------------
__device__ __half g_Xt_hi[DIM_D * DIM_N];    // X^T  [512, 4096]
__device__ __half g_CM_hi[DIM_CM * DIM_D];   // [C; M^T]  [6144, 512]
__device__ __half g_S_hi[DIM_D * DIM_D];     // S    [512, 512]
__device__ __half g_U_hi[DIM_K * DIM_D];     // U = C@S  [2048, 512]
__device__ float g_Spart[ZSPLIT * DIM_D * DIM_D];   // split-K partials
__device__ float g_dotp[4 * DIM_CM];                // per-col-band dot partials
__device__ float g_xm2[DIM_M];
__device__ float g_xc2[DIM_K];

// ---------------------------- warp-MMA helpers ------------------------------
__device__ __forceinline__ uint32_t smem_u32(const void* p) {
    uint32_t a;
    asm("{ .reg .u64 t; cvta.to.shared.u64 t, %1; cvt.u32.u64 %0, t; }" : "=r"(a) : "l"(p));
    return a;
}
__device__ __forceinline__ void ldm_x4(uint32_t* r, uint32_t addr) {
    asm volatile("ldmatrix.sync.aligned.m8n8.x4.shared.b16 {%0,%1,%2,%3}, [%4];"
                 : "=r"(r[0]), "=r"(r[1]), "=r"(r[2]), "=r"(r[3]) : "r"(addr));
}
__device__ __forceinline__ void mma_f16(float* c, const uint32_t* a, const uint32_t* b) {
    asm volatile("mma.sync.aligned.m16n8k16.row.col.f32.f16.f16.f32 "
                 "{%0,%1,%2,%3}, {%4,%5,%6,%7}, {%8,%9}, {%0,%1,%2,%3};"
                 : "+f"(c[0]), "+f"(c[1]), "+f"(c[2]), "+f"(c[3])
                 : "r"(a[0]), "r"(a[1]), "r"(a[2]), "r"(a[3]), "r"(b[0]), "r"(b[1]));
}
#define CP_ASYNC16(dst, src) \
    asm volatile("cp.async.cg.shared.global [%0], [%1], 16;" :: "r"(dst), "l"(src))
#define CP_COMMIT() asm volatile("cp.async.commit_group;" ::: "memory")
#define CP_WAIT1()  asm volatile("cp.async.wait_group 1;" ::: "memory")
#define CP_WAIT0()  asm volatile("cp.async.wait_group 0;" ::: "memory")

// 128B-row smem layout with XOR swizzle: 16B chunk column ^= (row & 7).
__device__ __forceinline__ uint32_t swz(uint32_t row, uint32_t col) {
    return row * 128 + (col ^ ((row & 7) << 4));
}

// ---------------------------------------------------------------------------
// Single-product fp16 GEMM via mma.sync:  G[i,j] = sum_k Ahi[i,k] * Bhi[j,k]
// A [Mo,Ktot] K-major fp16, B [No,Ktot] K-major fp16.
// CTA tile 128x128, K-slab 64, 256 threads = 8 warps (2x4), warp tile 64x32.
// 3-stage cp.async pipeline, 32KB stages (96KB smem, 2 CTA/SM).
// MODE 0: write fp32 Cout (with z-split offsets).
// MODE 1: fused distance epilogue: out = sqrt(max(colAdd[c] - 2g + rowAdd[r],0)).
// MODE 2: UT mode (Ktot==No==512): fp16 G -> Uhi (rows < DIM_K) + per-CTA-band
//         dot partials dotp[bx*DIM_CM+row] = sum_{c in band} Ahi[row,c]*G[row,c].
// ---------------------------------------------------------------------------
static constexpr int TILE_BYTES = 128 * 128;           // 16384
static constexpr int STAGE_BYTES = 2 * TILE_BYTES;     // 32768
static constexpr int GEMM_SMEM = 3 * STAGE_BYTES;      // 98304

template <int MODE>
__global__ __launch_bounds__(256, 2)
void f16s_gemm(const __half* __restrict__ Ahi,
               const __half* __restrict__ Bhi,
               float* __restrict__ Cout,
               int No, int Ktot, int kspan, size_t zstride,
               const float* __restrict__ rowAdd, const float* __restrict__ colAdd,
               __half* __restrict__ Uhi, float* __restrict__ dotp)
{
    extern __shared__ __align__(128) unsigned char smem[];
    const uint32_t sbase = smem_u32(smem);
    const uint32_t OFF_AHI = 0, OFF_BHI = TILE_BYTES;

    const int tid = threadIdx.x;
    const int wid = tid >> 5;
    const int lane = tid & 31;
    const int warp_m = wid >> 2;     // 0..1 -> 64 rows each
    const int warp_n = wid & 3;      // 0..3 -> 32 cols each
    const int rowA0 = blockIdx.y * 128;
    const int rowB0 = blockIdx.x * 128;
    const int kz = blockIdx.z * kspan;
    const int nslabs = kspan / 64;
    if (MODE == 0) Cout += (size_t)blockIdx.z * zstride;

    float acc[4][4][4];
#pragma unroll
    for (int i = 0; i < 4; i++)
#pragma unroll
        for (int j = 0; j < 4; j++)
#pragma unroll
            for (int v = 0; v < 4; v++) acc[i][j][v] = 0.0f;

    // ldmatrix lane addressing (k-invariant parts)
    const int a_row = warp_m * 64 + (lane & 15);
    const uint32_t a_coff = (uint32_t)((lane >> 4) << 4);
    const int b_row = warp_n * 32 + ((lane >> 4) << 3) + (lane & 7);
    const uint32_t b_coff = (uint32_t)(((lane >> 3) & 1) << 4);

    auto load_slab = [&](int slab, int stage) {
        const int kbase = kz + slab * 64;
        const uint32_t st = (uint32_t)stage * STAGE_BYTES;
#pragma unroll
        for (int i = 0; i < 4; i++) {
            const int idx = tid + i * 256;       // 0..1023
            const int r = idx >> 3;
            const int c = idx & 7;               // 16B chunk within 128B row
            const size_t aoff = (size_t)(rowA0 + r) * Ktot + kbase + c * 8;
            const size_t boff = (size_t)(rowB0 + r) * Ktot + kbase + c * 8;
            const uint32_t so = st + swz((uint32_t)r, (uint32_t)(c * 16));
            CP_ASYNC16(sbase + OFF_AHI + so, Ahi + aoff);
            CP_ASYNC16(sbase + OFF_BHI + so, Bhi + boff);
        }
    };

    // 3-stage pipeline: prefetch distance 2.
    load_slab(0, 0); CP_COMMIT();
    if (nslabs > 1) { load_slab(1, 1); CP_COMMIT(); }

    for (int slab = 0; slab < nslabs; slab++) {
        if (slab + 2 < nslabs) { CP_WAIT1(); } else { CP_WAIT0(); }
        __syncthreads();          // slab data visible; stage (slab+2)%3 free
        if (slab + 2 < nslabs) {
            load_slab(slab + 2, (slab + 2) % 3);
            CP_COMMIT();
        }

        const uint32_t st = (uint32_t)(slab % 3) * STAGE_BYTES;
#pragma unroll
        for (int kk = 0; kk < 4; kk++) {         // four k16 steps per slab
            const uint32_t kcol = kk * 32;
            uint32_t a_hi[4][4], b_hi[2][4];
#pragma unroll
            for (int mi = 0; mi < 4; mi++) {
                const uint32_t ar = st + swz((uint32_t)(a_row + mi * 16), kcol + a_coff);
                ldm_x4(a_hi[mi], sbase + OFF_AHI + ar);
            }
#pragma unroll
            for (int p = 0; p < 2; p++) {        // nj pairs {0,1}, {2,3}
                const uint32_t br = st + swz((uint32_t)(b_row + p * 16), kcol + b_coff);
                ldm_x4(b_hi[p], sbase + OFF_BHI + br);
            }
#pragma unroll
            for (int mi = 0; mi < 4; mi++)
#pragma unroll
                for (int nj = 0; nj < 4; nj++)
                    mma_f16(acc[mi][nj], a_hi[mi], &b_hi[nj >> 1][(nj & 1) * 2]);
        }
    }

    // ---------------- epilogue ----------------
    // c-frag layout: c0,c1 -> row lane/4, cols (lane%4)*2+{0,1}; c2,c3 -> row+8
    const int er0 = rowA0 + warp_m * 64 + (lane >> 2);
    const int ec0 = rowB0 + warp_n * 32 + (lane & 3) * 2;

    if (MODE == 2) {
        __syncthreads();                          // mainloop smem reuse
        float* sm_dot = (float*)smem;             // [128 rows][4 warp_n]
#pragma unroll
        for (int mi = 0; mi < 4; mi++) {
#pragma unroll
            for (int half = 0; half < 2; half++) {
                const int row = er0 + mi * 16 + half * 8;
                float rs = 0.0f;
#pragma unroll
                for (int nj = 0; nj < 4; nj++) {
                    const int col = ec0 + nj * 8;
                    float2 v;
                    v.x = acc[mi][nj][half * 2 + 0];
                    v.y = acc[mi][nj][half * 2 + 1];
                    const size_t o = (size_t)row * Ktot + col;
                    const float ax = __half2float(Ahi[o]);
                    const float ay = __half2float(Ahi[o + 1]);
                    rs = fmaf(ax, v.x, rs);
                    rs = fmaf(ay, v.y, rs);
                    if (row < DIM_K) {            // write U (fp16 hi only)
                        __half2 h2;
                        h2.x = __float2half_rn(v.x);
                        h2.y = __float2half_rn(v.y);
                        *(__half2*)(Uhi + (size_t)row * DIM_D + col) = h2;
                    }
                }
                rs += __shfl_xor_sync(0xFFFFFFFFu, rs, 1);
                rs += __shfl_xor_sync(0xFFFFFFFFu, rs, 2);
                if ((lane & 3) == 0) {
                    const int lr = warp_m * 64 + mi * 16 + half * 8 + (lane >> 2);
                    sm_dot[lr * 4 + warp_n] = rs;
                }
            }
        }
        __syncthreads();
        if (tid < 128) {
            const float s = sm_dot[tid * 4] + sm_dot[tid * 4 + 1]
                          + sm_dot[tid * 4 + 2] + sm_dot[tid * 4 + 3];
            dotp[(size_t)blockIdx.x * DIM_CM + rowA0 + tid] = s;
        }
        return;
    }

#pragma unroll
    for (int mi = 0; mi < 4; mi++) {
#pragma unroll
        for (int half = 0; half < 2; half++) {
            const int row = er0 + mi * 16 + half * 8;
            float radd = 0.0f;
            if (MODE == 1) radd = rowAdd[row];
#pragma unroll
            for (int nj = 0; nj < 4; nj++) {
                const int col = ec0 + nj * 8;
                float2 v;
                v.x = acc[mi][nj][half * 2 + 0];
                v.y = acc[mi][nj][half * 2 + 1];
                if (MODE == 1) {
                    const float2 ca = *(const float2*)(colAdd + col);
                    v.x = sqrtf(fmaxf(ca.x - 2.0f * v.x + radd, 0.0f));
                    v.y = sqrtf(fmaxf(ca.y - 2.0f * v.y + radd, 0.0f));
                }
                *(float2*)(Cout + (size_t)row * No + col) = v;
            }
        }
    }
}

// ------------------------- conversion / small kernels -----------------------
__global__ void half_kernel(const float* __restrict__ in,
                            __half* __restrict__ hi, int n)
{
    const int i = blockIdx.x * blockDim.x + threadIdx.x;
    if (i >= n) return;
    hi[i] = __float2half_rn(in[i]);
}

// in [R,C] fp32 -> hi [C,R] fp16 (transpose)
__global__ void half_transpose_kernel(const float* __restrict__ in,
                                      __half* __restrict__ hi, int R, int C)
{
    __shared__ float t[32][33];
    const int x = blockIdx.x * 32 + threadIdx.x;
    const int y0 = blockIdx.y * 32;
#pragma unroll
    for (int j = 0; j < 32; j += 8)
        t[threadIdx.y + j][threadIdx.x] = in[(size_t)(y0 + threadIdx.y + j) * C + x];
    __syncthreads();
#pragma unroll
    for (int j = 0; j < 32; j += 8) {
        const int c = blockIdx.x * 32 + threadIdx.y + j;
        const int r = y0 + threadIdx.x;
        hi[(size_t)c * R + r] = __float2half_rn(t[threadIdx.x][threadIdx.y + j]);
    }
}

// sum split-K partials of S -> fp16 hi
__global__ void reduce_split_kernel(const float* __restrict__ part,
                                    __half* __restrict__ hi, int n)
{
    const int i = blockIdx.x * blockDim.x + threadIdx.x;
    if (i >= n) return;
    float acc = 0.0f;
#pragma unroll
    for (int z = 0; z < ZSPLIT; z++) acc += part[i + (size_t)z * n];
    hi[i] = __float2half_rn(acc);
}

__global__ void combine_dots_kernel(const float* __restrict__ dotp,
                                    float* __restrict__ xc2, float* __restrict__ xm2)
{
    const int i = blockIdx.x * blockDim.x + threadIdx.x;
    if (i >= DIM_CM) return;
    const float s = dotp[i] + dotp[DIM_CM + i] + dotp[2 * DIM_CM + i] + dotp[3 * DIM_CM + i];
    if (i < DIM_K) xc2[i] = s;
    else           xm2[i - DIM_K] = s;
}

// --------------------------------- launch ----------------------------------
extern "C" void kernel_launch(void* const* d_in, const int* in_sizes, int n_in,
                              void* d_out, int out_size)
{
    const float* X = (const float*)d_in[0];  // [4096, 512]
    const float* M = (const float*)d_in[1];  // [512, 4096]
    const float* C = (const float*)d_in[2];  // [2048, 512]
    float* out = (float*)d_out;              // [2048, 4096]

    static bool attr_done = false;
    if (!attr_done) {
        cudaFuncSetAttribute(f16s_gemm<0>, cudaFuncAttributeMaxDynamicSharedMemorySize, GEMM_SMEM);
        cudaFuncSetAttribute(f16s_gemm<1>, cudaFuncAttributeMaxDynamicSharedMemorySize, GEMM_SMEM);
        cudaFuncSetAttribute(f16s_gemm<2>, cudaFuncAttributeMaxDynamicSharedMemorySize, GEMM_SMEM);
        attr_done = true;
    }

    __half *Xt_hi, *CM_hi, *S_hi, *U_hi;
    float *Spart, *dotp, *xm2, *xc2;
    cudaGetSymbolAddress((void**)&Xt_hi, g_Xt_hi);
    cudaGetSymbolAddress((void**)&CM_hi, g_CM_hi);
    cudaGetSymbolAddress((void**)&S_hi,  g_S_hi);
    cudaGetSymbolAddress((void**)&U_hi,  g_U_hi);
    cudaGetSymbolAddress((void**)&Spart, g_Spart);
    cudaGetSymbolAddress((void**)&dotp,  g_dotp);
    cudaGetSymbolAddress((void**)&xm2,   g_xm2);
    cudaGetSymbolAddress((void**)&xc2,   g_xc2);

    __half* Mt_hi = CM_hi + (size_t)DIM_K * DIM_D;  // rows 2048..6143

    // 1) fp16 conversions: Xt [512,4096]; CM = [C; M^T] [6144,512] (hi only)
    half_transpose_kernel<<<dim3(DIM_D / 32, DIM_N / 32), dim3(32, 8)>>>(X, Xt_hi, DIM_N, DIM_D);
    half_kernel<<<(DIM_K * DIM_D) / 256, 256>>>(C, CM_hi, DIM_K * DIM_D);
    half_transpose_kernel<<<dim3(DIM_M / 32, DIM_D / 32), dim3(32, 8)>>>(M, Mt_hi, DIM_D, DIM_M);

    // 2) S = Xt_hi @ Xt_hi^T  [512,512], K=4096, split-K=8 (8 slabs each)
    f16s_gemm<0><<<dim3(DIM_D / 128, DIM_D / 128, ZSPLIT), 256, GEMM_SMEM>>>(
        Xt_hi, Xt_hi, Spart,
        DIM_D, DIM_N, DIM_N / ZSPLIT, (size_t)DIM_D * DIM_D,
        nullptr, nullptr, nullptr, nullptr);
    reduce_split_kernel<<<(DIM_D * DIM_D) / 256, 256>>>(Spart, S_hi, DIM_D * DIM_D);

    // 3) UT = CM_hi @ S_hi  (MODE2: writes U_hi for C rows + dot partials)
    f16s_gemm<2><<<dim3(DIM_D / 128, DIM_CM / 128, 1), 256, GEMM_SMEM>>>(
        CM_hi, S_hi, nullptr, DIM_D, DIM_D, DIM_D, 0,
        nullptr, nullptr, U_hi, dotp);

    // 4) xc2[k] = c_k^T S c_k ; xm2[m] = m^T S m
    combine_dots_kernel<<<(DIM_CM + 255) / 256, 256>>>(dotp, xc2, xm2);

    // 5) out[k,m] = sqrt(max(xm2[m] - 2*(U_hi @ Mt_hi^T)[k,m] + xc2[k], 0))
    f16s_gemm<1><<<dim3(DIM_M / 128, DIM_K / 128, 1), 256, GEMM_SMEM>>>(
        U_hi, Mt_hi, out, DIM_M, DIM_D, DIM_D, 0,
        xc2, xm2, nullptr, nullptr);
}